// round 3
// baseline (speedup 1.0000x reference)
#include <cuda_runtime.h>

// Problem constants (fixed by the reference implementation)
#define NFEAT 23
#define EMB   10
#define TOTALD 65     // sum(FEATURE_DIMS)
#define DMAXD 4
#define CH    230     // NFEAT * EMB
#define PAIRS 115     // CH / 2 — each thread owns an (e, e+1) pair of one feature

__constant__ int c_dims[NFEAT] = {4,4,4,4,4,4,4,4,4,4,4,4,2,2,1,4,1,1,1,1,1,1,2};
__constant__ int c_offs[NFEAT] = {0,4,8,12,16,20,24,28,32,36,40,44,48,50,52,53,57,58,59,60,61,62,63};

// Thread layout: blockDim=256. tid%128 = pair index p (0..114 active),
// tid/128 = row phase (even/odd rows of this block's range).
// Each thread keeps its 8 weights + 2 biases in registers and streams rows:
//   per row:  <=4 predicated LDG (x), 8 FMA, 1 coalesced STG.64 (float2).
__global__ __launch_bounds__(256, 8)
void Projection_5171140624940_kernel(const float* __restrict__ x,
                                     const float* __restrict__ W,
                                     const float* __restrict__ b,
                                     float* __restrict__ out,
                                     int rows, int rows_per_block)
{
    const int p     = threadIdx.x & 127;
    const int rslot = threadIdx.x >> 7;
    if (p >= PAIRS) return;

    // channel pair c = 2p  ->  f = c/10 = p/5 ,  e = c%10 = 2*(p%5)
    const int f = p / 5;
    const int e = (p - f * 5) * 2;
    const int off = c_offs[f];
    const int dim = c_dims[f];

    // W layout: [F, DMAX, EMB] row-major -> W[f*40 + j*10 + e].
    // W is already zero-masked for j >= dim by the reference setup, but we
    // predicate the x loads anyway (also avoids OOB on the last feature).
    float w0[DMAXD], w1[DMAXD];
    #pragma unroll
    for (int j = 0; j < DMAXD; ++j) {
        w0[j] = __ldg(W + f * (DMAXD * EMB) + j * EMB + e);
        w1[j] = __ldg(W + f * (DMAXD * EMB) + j * EMB + e + 1);
    }
    const float b0 = __ldg(b + f * EMB + e);
    const float b1 = __ldg(b + f * EMB + e + 1);

    const int rBase = blockIdx.x * rows_per_block;
    const int rEnd  = min(rows, rBase + rows_per_block);

    #pragma unroll 4
    for (int r = rBase + rslot; r < rEnd; r += 2) {
        const float* xr = x + (size_t)r * TOTALD + off;
        float s0 = b0, s1 = b1;
        #pragma unroll
        for (int j = 0; j < DMAXD; ++j) {
            if (j < dim) {
                float xv = __ldg(xr + j);
                s0 = fmaf(xv, w0[j], s0);
                s1 = fmaf(xv, w1[j], s1);
            }
        }
        // out row base = r*920 bytes (8-aligned); lanes write contiguous
        // float2s -> fully coalesced 256B-per-warp stores.
        float2 o = make_float2(s0, s1);
        *reinterpret_cast<float2*>(out + (size_t)r * CH + 2 * p) = o;
    }
}

extern "C" void kernel_launch(void* const* d_in, const int* in_sizes, int n_in,
                              void* d_out, int out_size)
{
    const float* x = (const float*)d_in[0];   // input: [B, 65] f32
    const float* W = (const float*)d_in[1];   // W: [23, 4, 10] f32 (masked)
    const float* b = (const float*)d_in[2];   // b: [23, 10] f32
    // d_in[3] = idx (int32) — redundant, metadata is compile-time constant.
    float* out = (float*)d_out;               // out: [B, 23, 10] f32

    const int rows = in_sizes[0] / TOTALD;    // 524288
    const int RPB  = 128;                     // rows per block -> 4096 blocks
    const int grid = (rows + RPB - 1) / RPB;

    Projection_5171140624940_kernel<<<grid, 256>>>(x, W, b, out, rows, RPB);
}

// round 4
// speedup vs baseline: 1.3895x; 1.3895x over previous
#include <cuda_runtime.h>

// Problem constants (fixed by the reference implementation)
#define NFEAT  23
#define EMB    10
#define TOTALD 65      // sum(FEATURE_DIMS)
#define DMAXD  4
#define CH     230     // NFEAT * EMB
#define PAIRS  115     // CH / 2 — each thread owns an (e, e+1) pair of one feature
#define TR     32      // rows per smem tile
#define RPB    128     // rows per block (multiple of TR; RPB*65*4 base stays 16B-aligned)

__constant__ int c_dims[NFEAT] = {4,4,4,4,4,4,4,4,4,4,4,4,2,2,1,4,1,1,1,1,1,1,2};
__constant__ int c_offs[NFEAT] = {0,4,8,12,16,20,24,28,32,36,40,44,48,50,52,53,57,58,59,60,61,62,63};

// Layout: blockDim=256. tid%128 = pair index p (0..114 active), tid/128 = row
// phase. Per tile: (A) all 256 threads stream the 32x65 f32 x-tile into smem
// with coalesced float4 __ldcs (each byte of x loaded exactly once);
// (B) active threads compute their channel pair from smem (conflict-free LDS:
// one row per warp, address span < 32 banks, duplicates broadcast) and emit
// one coalesced float2 streaming store per row.
__global__ __launch_bounds__(256, 8)
void Projection_5171140624940_kernel(const float* __restrict__ x,
                                     const float* __restrict__ W,
                                     const float* __restrict__ b,
                                     float* __restrict__ out,
                                     int rows)
{
    __shared__ float xs[TR * TOTALD];   // 8320 B

    const int tid   = threadIdx.x;
    const int p     = tid & 127;
    const int rslot = tid >> 7;
    const bool active = (p < PAIRS);

    // Per-thread channel pair metadata + register-resident weights.
    float w0[DMAXD], w1[DMAXD];
    float b0 = 0.f, b1 = 0.f;
    int off = 0, dim = 0;
    if (active) {
        const int f = p / 5;
        const int e = (p - f * 5) * 2;
        off = c_offs[f];
        dim = c_dims[f];
        #pragma unroll
        for (int j = 0; j < DMAXD; ++j) {
            w0[j] = __ldg(W + f * (DMAXD * EMB) + j * EMB + e);
            w1[j] = __ldg(W + f * (DMAXD * EMB) + j * EMB + e + 1);
        }
        b0 = __ldg(b + f * EMB + e);
        b1 = __ldg(b + f * EMB + e + 1);
    }

    const int rBase = blockIdx.x * RPB;

    for (int t0 = 0; t0 < RPB; t0 += TR) {
        const int tileStart = rBase + t0;
        if (tileStart >= rows) break;
        const int tileRows = min(TR, rows - tileStart);

        // ---- Phase A: stage x tile into smem ----
        if (tileRows == TR) {
            // Fast path: 2080 floats = 520 float4, base is 16B-aligned
            // (tileStart is a multiple of 32 -> tileStart*65*4 % 16 == 0).
            const float4* src = reinterpret_cast<const float4*>(
                x + (size_t)tileStart * TOTALD);
            float4* dst = reinterpret_cast<float4*>(xs);
            #pragma unroll
            for (int i = tid; i < (TR * TOTALD) / 4; i += 256)
                dst[i] = __ldcs(src + i);
        } else {
            const float* src = x + (size_t)tileStart * TOTALD;
            for (int i = tid; i < tileRows * TOTALD; i += 256)
                xs[i] = __ldcs(src + i);
        }
        __syncthreads();

        // ---- Phase B: compute + streaming stores ----
        if (active) {
            #pragma unroll 4
            for (int lr = rslot; lr < tileRows; lr += 2) {
                const float* xr = xs + lr * TOTALD + off;
                float s0 = b0, s1 = b1;
                #pragma unroll
                for (int j = 0; j < DMAXD; ++j) {
                    if (j < dim) {
                        const float xv = xr[j];
                        s0 = fmaf(xv, w0[j], s0);
                        s1 = fmaf(xv, w1[j], s1);
                    }
                }
                const size_t r = (size_t)(tileStart + lr);
                // warp writes 256B contiguous; .cs keeps the 482MB output
                // stream out of L2's way.
                __stcs(reinterpret_cast<float2*>(out + r * CH + 2 * p),
                       make_float2(s0, s1));
            }
        }
        __syncthreads();
    }
}

extern "C" void kernel_launch(void* const* d_in, const int* in_sizes, int n_in,
                              void* d_out, int out_size)
{
    const float* x = (const float*)d_in[0];   // [B, 65] f32
    const float* W = (const float*)d_in[1];   // [23, 4, 10] f32 (masked)
    const float* b = (const float*)d_in[2];   // [23, 10] f32
    // d_in[3] = idx (int32) — compile-time constant metadata, ignored.
    float* out = (float*)d_out;               // [B, 23, 10] f32

    const int rows = in_sizes[0] / TOTALD;    // 524288
    const int grid = (rows + RPB - 1) / RPB;  // 4096

    Projection_5171140624940_kernel<<<grid, 256>>>(x, W, b, out, rows);
}

// round 5
// speedup vs baseline: 1.4499x; 1.0434x over previous
#include <cuda_runtime.h>
#include <cstdint>

// Problem constants (fixed by the reference implementation)
#define NFEAT  23
#define EMB    10
#define TOTALD 65      // sum(FEATURE_DIMS)
#define DMAXD  4
#define CH     230     // NFEAT * EMB
#define PAIRS  115     // CH / 2 — each thread owns an (e, e+1) pair of one feature
#define TR     32      // rows per smem tile
#define NTILES 4
#define RPB    (TR * NTILES)   // 128 rows per block
#define TILE_F4 ((TR * TOTALD) / 4)   // 520 float4 per tile

__constant__ int c_dims[NFEAT] = {4,4,4,4,4,4,4,4,4,4,4,4,2,2,1,4,1,1,1,1,1,1,2};
__constant__ int c_offs[NFEAT] = {0,4,8,12,16,20,24,28,32,36,40,44,48,50,52,53,57,58,59,60,61,62,63};

__device__ __forceinline__ void cp_async16(void* smem_dst, const void* gsrc) {
    uint32_t s = (uint32_t)__cvta_generic_to_shared(smem_dst);
    asm volatile("cp.async.cg.shared.global [%0], [%1], 16;\n" :: "r"(s), "l"(gsrc));
}
#define CP_COMMIT() asm volatile("cp.async.commit_group;\n" ::: "memory")
#define CP_WAIT1()  asm volatile("cp.async.wait_group 1;\n" ::: "memory")
#define CP_WAIT0()  asm volatile("cp.async.wait_group 0;\n" ::: "memory")

// blockDim=256. tid%128 = channel-pair index p (0..114 active), tid/128 = row
// phase. Double-buffered cp.async pipeline: tile t+1 streams GMEM->SMEM
// (no register round-trip, L1-bypass) while tile t is computed and stored
// with coalesced float2 streaming stores (256B/warp contiguous).
__global__ __launch_bounds__(256, 8)
void Projection_5171140624940_kernel(const float* __restrict__ x,
                                     const float* __restrict__ W,
                                     const float* __restrict__ b,
                                     float* __restrict__ out,
                                     int rows)
{
    __shared__ __align__(16) float xs[2][TR * TOTALD];   // 2 x 8320 B

    const int tid   = threadIdx.x;
    const int p     = tid & 127;
    const int rslot = tid >> 7;
    const bool active = (p < PAIRS);

    // Per-thread channel-pair metadata + register-resident weights.
    float w0[DMAXD], w1[DMAXD];
    float b0 = 0.f, b1 = 0.f;
    int off = 0, dim = 0;
    if (active) {
        const int f = p / 5;
        const int e = (p - f * 5) * 2;
        off = c_offs[f];
        dim = c_dims[f];
        #pragma unroll
        for (int j = 0; j < DMAXD; ++j) {
            w0[j] = __ldg(W + f * (DMAXD * EMB) + j * EMB + e);
            w1[j] = __ldg(W + f * (DMAXD * EMB) + j * EMB + e + 1);
        }
        b0 = __ldg(b + f * EMB + e);
        b1 = __ldg(b + f * EMB + e + 1);
    }

    const int rBase = blockIdx.x * RPB;

    if (rBase + RPB <= rows) {
        // ---- Fast path: full block of 4 complete tiles, async pipeline ----
        // Prefetch tile 0 (gmem base rBase*65*4 is 16B-aligned: rBase % 128 == 0).
        {
            const float4* src = reinterpret_cast<const float4*>(
                x + (size_t)rBase * TOTALD);
            float4* dst = reinterpret_cast<float4*>(xs[0]);
            #pragma unroll
            for (int i = tid; i < TILE_F4; i += 256)
                cp_async16(dst + i, src + i);
        }
        CP_COMMIT();

        #pragma unroll
        for (int t = 0; t < NTILES; ++t) {
            const int buf = t & 1;
            if (t + 1 < NTILES) {
                const float4* src = reinterpret_cast<const float4*>(
                    x + (size_t)(rBase + (t + 1) * TR) * TOTALD);
                float4* dst = reinterpret_cast<float4*>(xs[buf ^ 1]);
                #pragma unroll
                for (int i = tid; i < TILE_F4; i += 256)
                    cp_async16(dst + i, src + i);
                CP_COMMIT();
                CP_WAIT1();          // tile t landed; t+1 may still be in flight
            } else {
                CP_WAIT0();
            }
            __syncthreads();

            if (active) {
                const int tileStart = rBase + t * TR;
                #pragma unroll 4
                for (int lr = rslot; lr < TR; lr += 2) {
                    const float* xr = xs[buf] + lr * TOTALD + off;
                    float s0 = b0, s1 = b1;
                    #pragma unroll
                    for (int j = 0; j < DMAXD; ++j) {
                        if (j < dim) {
                            const float xv = xr[j];
                            s0 = fmaf(xv, w0[j], s0);
                            s1 = fmaf(xv, w1[j], s1);
                        }
                    }
                    __stcs(reinterpret_cast<float2*>(
                               out + (size_t)(tileStart + lr) * CH + 2 * p),
                           make_float2(s0, s1));
                }
            }
            __syncthreads();   // buf is re-filled 2 iterations later; safe
        }
    } else {
        // ---- Tail path (not hit for B=524288): synchronous staging ----
        for (int t0 = 0; t0 < RPB; t0 += TR) {
            const int tileStart = rBase + t0;
            if (tileStart >= rows) break;
            const int tileRows = min(TR, rows - tileStart);

            const float* src = x + (size_t)tileStart * TOTALD;
            for (int i = tid; i < tileRows * TOTALD; i += 256)
                xs[0][i] = __ldcs(src + i);
            __syncthreads();

            if (active) {
                for (int lr = rslot; lr < tileRows; lr += 2) {
                    const float* xr = xs[0] + lr * TOTALD + off;
                    float s0 = b0, s1 = b1;
                    #pragma unroll
                    for (int j = 0; j < DMAXD; ++j) {
                        if (j < dim) {
                            const float xv = xr[j];
                            s0 = fmaf(xv, w0[j], s0);
                            s1 = fmaf(xv, w1[j], s1);
                        }
                    }
                    __stcs(reinterpret_cast<float2*>(
                               out + (size_t)(tileStart + lr) * CH + 2 * p),
                           make_float2(s0, s1));
                }
            }
            __syncthreads();
        }
    }
}

extern "C" void kernel_launch(void* const* d_in, const int* in_sizes, int n_in,
                              void* d_out, int out_size)
{
    const float* x = (const float*)d_in[0];   // [B, 65] f32
    const float* W = (const float*)d_in[1];   // [23, 4, 10] f32 (masked)
    const float* b = (const float*)d_in[2];   // [23, 10] f32
    // d_in[3] = idx (int32) — compile-time constant metadata, ignored.
    float* out = (float*)d_out;               // [B, 23, 10] f32

    const int rows = in_sizes[0] / TOTALD;    // 524288
    const int grid = (rows + RPB - 1) / RPB;  // 4096

    Projection_5171140624940_kernel<<<grid, 256>>>(x, W, b, out, rows);
}